// round 16
// baseline (speedup 1.0000x reference)
#include <cuda_runtime.h>
#include <cuda_bf16.h>
#include <stdint.h>
#include <math.h>

#define NB 4
#define NS 2048
#define NE 1024
#define ND 128
#define NTOK 8192

typedef __nv_bfloat16 bf;

// ---------------- device scratch (allocation-free) ----------------
__device__ float g_s [(size_t)NTOK * NS];            // 64 MB scores
__device__ bf g_Ph[(size_t)NTOK * NS];
__device__ bf g_Pl[(size_t)NTOK * NS];
__device__ bf g_qh[NTOK * ND], g_ql[NTOK * ND];
__device__ bf g_kh[NTOK * ND], g_kl[NTOK * ND];
__device__ bf g_vh[NTOK * ND], g_vl[NTOK * ND];      // [tok][d]
__device__ bf g_wh[3 * NE * ND], g_wl[3 * NE * ND];  // [mat][e][d]

// ---------------- helpers ----------------
__device__ __forceinline__ uint32_t s2u(const void* p) {
    uint32_t a;
    asm("{ .reg .u64 t; cvta.to.shared.u64 t, %1; cvt.u32.u64 %0, t; }" : "=r"(a) : "l"(p));
    return a;
}
__device__ __forceinline__ void ldsm4(uint32_t& r0, uint32_t& r1, uint32_t& r2, uint32_t& r3, uint32_t a) {
    asm volatile("ldmatrix.sync.aligned.m8n8.x4.shared.b16 {%0,%1,%2,%3}, [%4];"
        : "=r"(r0), "=r"(r1), "=r"(r2), "=r"(r3) : "r"(a));
}
__device__ __forceinline__ void ldsm4t(uint32_t& r0, uint32_t& r1, uint32_t& r2, uint32_t& r3, uint32_t a) {
    asm volatile("ldmatrix.sync.aligned.m8n8.x4.trans.shared.b16 {%0,%1,%2,%3}, [%4];"
        : "=r"(r0), "=r"(r1), "=r"(r2), "=r"(r3) : "r"(a));
}
__device__ __forceinline__ void mma16816(float* c,
    uint32_t a0, uint32_t a1, uint32_t a2, uint32_t a3, uint32_t b0, uint32_t b1) {
    asm volatile("mma.sync.aligned.m16n8k16.row.col.f32.bf16.bf16.f32 "
        "{%0,%1,%2,%3}, {%4,%5,%6,%7}, {%8,%9}, {%0,%1,%2,%3};"
        : "+f"(c[0]), "+f"(c[1]), "+f"(c[2]), "+f"(c[3])
        : "r"(a0), "r"(a1), "r"(a2), "r"(a3), "r"(b0), "r"(b1));
}
__device__ __forceinline__ void cpa16(uint32_t s, const void* g) {
    asm volatile("cp.async.cg.shared.global [%0], [%1], 16;" :: "r"(s), "l"(g) : "memory");
}
__device__ __forceinline__ void cpa_commit() {
    asm volatile("cp.async.commit_group;" ::: "memory");
}
template<int N> __device__ __forceinline__ void cpa_wait() {
    asm volatile("cp.async.wait_group %0;" :: "n"(N) : "memory");
}
__device__ __forceinline__ void split2(float a, float b, uint32_t& hi, uint32_t& lo) {
    bf ha = __float2bfloat16(a), hb = __float2bfloat16(b);
    bf la = __float2bfloat16(a - __bfloat162float(ha));
    bf lb = __float2bfloat16(b - __bfloat162float(hb));
    __nv_bfloat162 H, L;
    H.x = ha; H.y = hb; L.x = la; L.y = lb;
    hi = *(uint32_t*)&H; lo = *(uint32_t*)&L;
}
__device__ __forceinline__ void tri_decode(int bidx, int& bi, int& bj) {
    int r = (int)((sqrtf(8.f * bidx + 1.f) - 1.f) * 0.5f);
    while ((r + 1) * (r + 2) / 2 <= bidx) r++;
    while (r * (r + 1) / 2 > bidx) r--;
    bi = r; bj = bidx - r * (r + 1) / 2;
}

// Warp-level split-bf16 GEMM over a K=32 span. NW: n 16-col tiles per warp.
// 3 passes (hh, hl, lh) for ILP.
template<int NW, int AS, int BS, int TRANSB>
__device__ __forceinline__ void compute32nw(float (*acc)[4],
    uint32_t Ah, uint32_t Al, uint32_t Bh, uint32_t Bl,
    int ak0, int bk0, int lane, int rowbase, int colbase)
{
    const uint32_t arow = rowbase + (lane & 15);
    #pragma unroll
    for (int ks = 0; ks < 2; ks++) {
        uint32_t ah[4], al[4];
        {
            uint32_t off = (arow * AS + ak0 + ks * 16 + ((lane >> 4) & 1) * 8) * 2;
            ldsm4(ah[0], ah[1], ah[2], ah[3], Ah + off);
            ldsm4(al[0], al[1], al[2], al[3], Al + off);
        }
        uint32_t bh[NW][4], bl[NW][4];
        #pragma unroll
        for (int p = 0; p < NW; p++) {
            if (TRANSB) {
                uint32_t off = ((uint32_t)(bk0 + ks * 16 + (lane & 15)) * BS
                              + colbase + p * 16 + ((lane >> 4) & 1) * 8) * 2;
                ldsm4t(bh[p][0], bh[p][1], bh[p][2], bh[p][3], Bh + off);
                ldsm4t(bl[p][0], bl[p][1], bl[p][2], bl[p][3], Bl + off);
            } else {
                uint32_t off = ((uint32_t)(colbase + p * 16 + (lane & 7) + ((lane >> 4) & 1) * 8) * BS
                              + bk0 + ks * 16 + ((lane >> 3) & 1) * 8) * 2;
                ldsm4(bh[p][0], bh[p][1], bh[p][2], bh[p][3], Bh + off);
                ldsm4(bl[p][0], bl[p][1], bl[p][2], bl[p][3], Bl + off);
            }
        }
        #pragma unroll
        for (int p = 0; p < NW; p++) {
            mma16816(acc[2 * p],     ah[0], ah[1], ah[2], ah[3], bh[p][0], bh[p][1]);
            mma16816(acc[2 * p + 1], ah[0], ah[1], ah[2], ah[3], bh[p][2], bh[p][3]);
        }
        #pragma unroll
        for (int p = 0; p < NW; p++) {
            mma16816(acc[2 * p],     ah[0], ah[1], ah[2], ah[3], bl[p][0], bl[p][1]);
            mma16816(acc[2 * p + 1], ah[0], ah[1], ah[2], ah[3], bl[p][2], bl[p][3]);
        }
        #pragma unroll
        for (int p = 0; p < NW; p++) {
            mma16816(acc[2 * p],     al[0], al[1], al[2], al[3], bh[p][0], bh[p][1]);
            mma16816(acc[2 * p + 1], al[0], al[1], al[2], al[3], bh[p][2], bh[p][3]);
        }
    }
}

// ---------------- prepass: split W only (x split folded into qkv) ----------------
__global__ __launch_bounds__(256) void wsplit_kernel(const float* __restrict__ wq,
    const float* __restrict__ wk, const float* __restrict__ wv) {
    const float* w = blockIdx.y == 0 ? wq : (blockIdx.y == 1 ? wk : wv);
    int i = blockIdx.x * 256 + threadIdx.x;
    float f = w[i];
    bf h = __float2bfloat16(f);
    bf l = __float2bfloat16(f - __bfloat162float(h));
    size_t o = (size_t)blockIdx.y * NE * ND + i;
    g_wh[o] = h; g_wl[o] = l;
}

// ---------------- kernel 1: QKV projection — A = fp32 x, split inline ----------------
// 3-stage ring. Stage: Ah 5120 | Al 5120 | Bh 8704 | Bl 8704 = 27648.
// A path: LDG fp32 two chunks ahead -> split in regs -> STS one iter before use.
#define QKV_STAGE 27648u
__global__ __launch_bounds__(256) void qkv_mma(const float* __restrict__ x,
    const float* __restrict__ bq, const float* __restrict__ bk, const float* __restrict__ bv)
{
    extern __shared__ __align__(16) char sm[];
    const uint32_t sb = s2u(sm);
    const int tid = threadIdx.x, lane = tid & 31, wid = tid >> 5;
    const int warpM = wid >> 1, warpN = wid & 1;
    const int m0 = blockIdx.x * 64, mat = blockIdx.y;

    float acc[8][4];
    #pragma unroll
    for (int i = 0; i < 8; i++)
        #pragma unroll
        for (int j = 0; j < 4; j++) acc[i][j] = 0.f;

    // A mapping: arow = tid>>2 (0..63), acol = (tid&3)*8 -> 8 floats/thread/chunk
    const int arow = tid >> 2, acol = (tid & 3) * 8;
    const float* gA = x + (size_t)(m0 + arow) * NE + acol;
    const uint32_t aoff = (uint32_t)(arow * 40 + acol) * 2;   // 16B-aligned

    // B loader (cp.async, proven path)
    auto load_B = [&](int st, int kb) {
        uint32_t stg = sb + st * QKV_STAGE + 10240u;
        #pragma unroll
        for (int i = 0; i < 4; i++) {
            int sidx = tid + i * 256;
            int split = sidx >> 9, r = (sidx & 511) >> 4, seg = sidx & 15;
            const bf* src = (split ? g_wl : g_wh) + ((size_t)mat * NE + kb + r) * ND + seg * 8;
            cpa16(stg + split * 8704 + r * 272 + seg * 16, src);
        }
        cpa_commit();
    };
    // A store: split regs -> stage smem (hi uint4 + lo uint4)
    auto sts_A = [&](int st, const float4* fA) {
        uint32_t stg = sb + st * QKV_STAGE;
        uint4 H, L;
        split2(fA[0].x, fA[0].y, H.x, L.x);
        split2(fA[0].z, fA[0].w, H.y, L.y);
        split2(fA[1].x, fA[1].y, H.z, L.z);
        split2(fA[1].z, fA[1].w, H.w, L.w);
        *(uint4*)(sm + (stg - sb) + aoff)         = H;
        *(uint4*)(sm + (stg - sb) + 5120u + aoff) = L;
    };

    float4 fA[2];
    // prologue: chunk0 -> stage0; prefetch chunk1; B stages 0,1
    fA[0] = ((const float4*)gA)[0];
    fA[1] = ((const float4*)gA)[1];
    sts_A(0, fA);
    fA[0] = ((const float4*)(gA + 32))[0];
    fA[1] = ((const float4*)(gA + 32))[1];
    load_B(0, 0);
    load_B(1, 32);

    for (int c = 0; c < 32; c++) {
        if (c + 1 < 32) sts_A((c + 1) % 3, fA);   // regs hold chunk c+1; stage (c+1)%3 free
        if (c >= 31) cpa_wait<0>(); else cpa_wait<1>();
        __syncthreads();
        uint32_t stg = sb + (uint32_t)(c % 3) * QKV_STAGE;
        compute32nw<4, 40, 136, 1>(acc, stg, stg + 5120, stg + 10240, stg + 10240 + 8704,
                                   0, 0, lane, warpM * 16, warpN * 64);
        if (c + 2 < 32) {
            load_B((c + 2) % 3, (c + 2) * 32);
            fA[0] = ((const float4*)(gA + (c + 2) * 32))[0];
            fA[1] = ((const float4*)(gA + (c + 2) * 32))[1];
        }
    }

    const float* bias = mat == 0 ? bq : (mat == 1 ? bk : bv);
    bf* oh = mat == 0 ? g_qh : (mat == 1 ? g_kh : g_vh);
    bf* ol = mat == 0 ? g_ql : (mat == 1 ? g_kl : g_vl);
    const int row = m0 + warpM * 16 + (lane >> 2);
    #pragma unroll
    for (int n = 0; n < 8; n++) {
        int col = warpN * 64 + n * 8 + 2 * (lane & 3);
        float b0 = __ldg(bias + col), b1 = __ldg(bias + col + 1);
        uint32_t H, L;
        split2(acc[n][0] + b0, acc[n][1] + b1, H, L);
        *(uint32_t*)(oh + (size_t)row * ND + col) = H;
        *(uint32_t*)(ol + (size_t)row * ND + col) = L;
        split2(acc[n][2] + b0, acc[n][3] + b1, H, L);
        *(uint32_t*)(oh + (size_t)(row + 8) * ND + col) = H;
        *(uint32_t*)(ol + (size_t)(row + 8) * ND + col) = L;
    }
}

// ---------------- kernel 2: scores (R8-proven tile-parallel M64) ----------------
__global__ __launch_bounds__(256) void scores_mma()
{
    extern __shared__ __align__(16) char sm[];
    const uint32_t sb = s2u(sm);
    const int tid = threadIdx.x, lane = tid & 31, wid = tid >> 5;
    const int warpM = wid >> 1, warpN = wid & 1;
    int bi, bj; tri_decode(blockIdx.x, bi, bj);
    const int b = blockIdx.y, i0 = bi * 128 + blockIdx.z * 64, j0 = bj * 128;

    float acc[8][4];
    #pragma unroll
    for (int i = 0; i < 8; i++)
        #pragma unroll
        for (int j = 0; j < 4; j++) acc[i][j] = 0.f;

    const size_t qbase = (size_t)(b * NS + i0) * ND;
    const size_t kbase = (size_t)(b * NS + j0) * ND;

    auto load_group = [&](int kb) {
        #pragma unroll
        for (int i = 0; i < 4; i++) {                 // A: 64 rows x 8 segs x2
            int sidx = tid + i * 256;
            int split = sidx >> 9, r = (sidx & 511) >> 3, seg = sidx & 7;
            const bf* src = (split ? g_ql : g_qh) + qbase + (size_t)r * ND + kb + seg * 8;
            cpa16(sb + split * 17408 + r * 272 + (kb + seg * 8) * 2, src);
        }
        #pragma unroll
        for (int i = 0; i < 8; i++) {                 // B: 128 rows x 8 segs x2
            int sidx = tid + i * 256;
            int split = sidx >> 10, r = (sidx & 1023) >> 3, seg = sidx & 7;
            const bf* src = (split ? g_kl : g_kh) + kbase + (size_t)r * ND + kb + seg * 8;
            cpa16(sb + 34816 + split * 34816 + r * 272 + (kb + seg * 8) * 2, src);
        }
        cpa_commit();
    };
    load_group(0);
    load_group(64);
    cpa_wait<1>(); __syncthreads();
    compute32nw<4, 136, 136, 0>(acc, sb, sb + 17408, sb + 34816, sb + 69632,  0,  0, lane, warpM * 16, warpN * 64);
    compute32nw<4, 136, 136, 0>(acc, sb, sb + 17408, sb + 34816, sb + 69632, 32, 32, lane, warpM * 16, warpN * 64);
    cpa_wait<0>(); __syncthreads();
    compute32nw<4, 136, 136, 0>(acc, sb, sb + 17408, sb + 34816, sb + 69632, 64, 64, lane, warpM * 16, warpN * 64);
    compute32nw<4, 136, 136, 0>(acc, sb, sb + 17408, sb + 34816, sb + 69632, 96, 96, lane, warpM * 16, warpN * 64);

    float* sout = g_s + ((size_t)b << 22);
    const float scale = 0.08838834764831845f;
    const int gi = i0 + warpM * 16 + (lane >> 2);
    #pragma unroll
    for (int n = 0; n < 8; n++) {
        int gj = j0 + warpN * 64 + n * 8 + 2 * (lane & 3);
        float2 v0, v1;
        v0.x = (gj     <= gi) ? acc[n][0] * scale : -INFINITY;
        v0.y = (gj + 1 <= gi) ? acc[n][1] * scale : -INFINITY;
        v1.x = (gj     <= gi + 8) ? acc[n][2] * scale : -INFINITY;
        v1.y = (gj + 1 <= gi + 8) ? acc[n][3] * scale : -INFINITY;
        *(float2*)(sout + (size_t)gi * NS + gj) = v0;
        *(float2*)(sout + (size_t)(gi + 8) * NS + gj) = v1;
    }
}

// ---------------- kernel 3: softmax -> split-bf16 P (R8-proven) ----------------
__global__ __launch_bounds__(256) void softmax_kernel() {
    __shared__ __align__(16) float buf[2048];
    __shared__ float red[8];
    const int rrow = blockIdx.x;
    const int b = rrow >> 11, i = rrow & 2047;
    const float4* s4 = (const float4*)(g_s + ((size_t)b << 22) + (size_t)i * NS);
    const int n4 = (((i >> 7) + 1) << 7) >> 2;
    const int tid = threadIdx.x, lane = tid & 31, wid = tid >> 5;
    float4* b4 = (float4*)buf;

    float m = -INFINITY;
    for (int j = tid; j < n4; j += 256) {
        float4 v = s4[j]; b4[j] = v;
        m = fmaxf(m, fmaxf(fmaxf(v.x, v.y), fmaxf(v.z, v.w)));
    }
    #pragma unroll
    for (int o = 16; o; o >>= 1) m = fmaxf(m, __shfl_xor_sync(0xffffffffu, m, o));
    if (lane == 0) red[wid] = m;
    __syncthreads();
    m = red[0];
    #pragma unroll
    for (int w = 1; w < 8; w++) m = fmaxf(m, red[w]);
    __syncthreads();

    float sum = 0.f;
    for (int j = tid; j < n4; j += 256) {
        float4 v = b4[j];
        v.x = __expf(v.x - m); v.y = __expf(v.y - m);
        v.z = __expf(v.z - m); v.w = __expf(v.w - m);
        b4[j] = v;
        sum += (v.x + v.y) + (v.z + v.w);
    }
    #pragma unroll
    for (int o = 16; o; o >>= 1) sum += __shfl_xor_sync(0xffffffffu, sum, o);
    if (lane == 0) red[wid] = sum;
    __syncthreads();
    sum = red[0];
    #pragma unroll
    for (int w = 1; w < 8; w++) sum += red[w];

    const float inv = 1.f / sum;
    uint2* ph = (uint2*)(g_Ph + (size_t)rrow * NS);
    uint2* pl = (uint2*)(g_Pl + (size_t)rrow * NS);
    for (int j = tid; j < n4; j += 256) {
        float4 v = b4[j];
        uint32_t h0, l0, h1, l1;
        split2(v.x * inv, v.y * inv, h0, l0);
        split2(v.z * inv, v.w * inv, h1, l1);
        ph[j] = make_uint2(h0, h1);
        pl[j] = make_uint2(l0, l1);
    }
}

// ---------------- kernel 4: P.V (R8-proven M64 full-K, atomics) ----------------
__global__ __launch_bounds__(256) void pv_mma(float* __restrict__ out)
{
    extern __shared__ __align__(16) char sm[];
    const uint32_t sb = s2u(sm);
    const int tid = threadIdx.x, lane = tid & 31, wid = tid >> 5;
    const int warpM = wid >> 1, warpN = wid & 1;
    int bi, bj; tri_decode(blockIdx.x, bi, bj);
    const int b = blockIdx.y, i0 = bi * 128 + blockIdx.z * 64, j0 = bj * 128;

    float acc[8][4];
    #pragma unroll
    for (int i = 0; i < 8; i++)
        #pragma unroll
        for (int j = 0; j < 4; j++) acc[i][j] = 0.f;

    const size_t pbase = (size_t)(b * NS + i0) * NS + j0;
    const size_t vbase = (size_t)(b * NS + j0) * ND;

    auto load_group = [&](int kb) {
        #pragma unroll
        for (int i = 0; i < 4; i++) {                 // A = P: 64 rows x 8 segs x2
            int sidx = tid + i * 256;
            int split = sidx >> 9, r = (sidx & 511) >> 3, seg = sidx & 7;
            const bf* src = (split ? g_Pl : g_Ph) + pbase + (size_t)r * NS + kb + seg * 8;
            cpa16(sb + split * 17408 + r * 272 + (kb + seg * 8) * 2, src);
        }
        #pragma unroll
        for (int i = 0; i < 8; i++) {                 // B = V: 64 k-rows x 16 segs x2
            int sidx = tid + i * 256;
            int split = sidx >> 10, r = (sidx & 1023) >> 4, seg = sidx & 15;
            const bf* src = (split ? g_vl : g_vh) + vbase + (size_t)(kb + r) * ND + seg * 8;
            cpa16(sb + 34816 + split * 34816 + (kb + r) * 272 + seg * 16, src);
        }
        cpa_commit();
    };
    load_group(0);
    load_group(64);
    cpa_wait<1>(); __syncthreads();
    compute32nw<4, 136, 136, 1>(acc, sb, sb + 17408, sb + 34816, sb + 69632,  0,  0, lane, warpM * 16, warpN * 64);
    compute32nw<4, 136, 136, 1>(acc, sb, sb + 17408, sb + 34816, sb + 69632, 32, 32, lane, warpM * 16, warpN * 64);
    cpa_wait<0>(); __syncthreads();
    compute32nw<4, 136, 136, 1>(acc, sb, sb + 17408, sb + 34816, sb + 69632, 64, 64, lane, warpM * 16, warpN * 64);
    compute32nw<4, 136, 136, 1>(acc, sb, sb + 17408, sb + 34816, sb + 69632, 96, 96, lane, warpM * 16, warpN * 64);

    const int gi = i0 + warpM * 16 + (lane >> 2);
    #pragma unroll
    for (int n = 0; n < 8; n++) {
        int gj = warpN * 64 + n * 8 + 2 * (lane & 3);
        float* o0 = out + (size_t)(b * NS + gi) * ND + gj;
        float* o1 = out + (size_t)(b * NS + gi + 8) * ND + gj;
        atomicAdd(o0,     acc[n][0]);
        atomicAdd(o0 + 1, acc[n][1]);
        atomicAdd(o1,     acc[n][2]);
        atomicAdd(o1 + 1, acc[n][3]);
    }
}

// ---------------- launch ----------------
extern "C" void kernel_launch(void* const* d_in, const int* in_sizes, int n_in,
                              void* d_out, int out_size) {
    const float* x  = (const float*)d_in[0];
    const float* wq = (const float*)d_in[1];
    const float* bq = (const float*)d_in[2];
    const float* wk = (const float*)d_in[3];
    const float* bk = (const float*)d_in[4];
    const float* wv = (const float*)d_in[5];
    const float* bv = (const float*)d_in[6];
    float* out = (float*)d_out;

    static int inited = 0;
    if (!inited) {
        cudaFuncSetAttribute(qkv_mma,    cudaFuncAttributeMaxDynamicSharedMemorySize, 3 * QKV_STAGE);
        cudaFuncSetAttribute(scores_mma, cudaFuncAttributeMaxDynamicSharedMemorySize, 104448);
        cudaFuncSetAttribute(pv_mma,     cudaFuncAttributeMaxDynamicSharedMemorySize, 104448);
        inited = 1;
    }

    cudaMemsetAsync(out, 0, (size_t)out_size * sizeof(float));
    wsplit_kernel<<<dim3(NE * ND / 256, 3), 256>>>(wq, wk, wv);
    qkv_mma<<<dim3(128, 3), 256, 3 * QKV_STAGE>>>(x, bq, bk, bv);
    scores_mma<<<dim3(136, NB, 2), 256, 104448>>>();
    softmax_kernel<<<NB * NS, 256>>>();
    pv_mma<<<dim3(136, NB, 2), 256, 104448>>>(out);
}

// round 17
// speedup vs baseline: 1.0918x; 1.0918x over previous
#include <cuda_runtime.h>
#include <cuda_bf16.h>
#include <stdint.h>
#include <math.h>

#define NB 4
#define NS 2048
#define NE 1024
#define ND 128
#define NTOK 8192

typedef __nv_bfloat16 bf;

// ---------------- device scratch (allocation-free) ----------------
__device__ float  g_po[(size_t)NB * 16 * 16 * 16384];   // partial O tiles, 67 MB
__device__ float2 g_stat[(size_t)NTOK * 16];            // per (row, j-tile) (m, sum)
__device__ bf g_xh[NTOK * NE], g_xl[NTOK * NE];
__device__ bf g_qh[NTOK * ND], g_ql[NTOK * ND];
__device__ bf g_kh[NTOK * ND], g_kl[NTOK * ND];
__device__ bf g_vh[NTOK * ND], g_vl[NTOK * ND];         // [tok][d]
__device__ bf g_wh[3 * NE * ND], g_wl[3 * NE * ND];     // [mat][e][d]

// ---------------- helpers ----------------
__device__ __forceinline__ uint32_t s2u(const void* p) {
    uint32_t a;
    asm("{ .reg .u64 t; cvta.to.shared.u64 t, %1; cvt.u32.u64 %0, t; }" : "=r"(a) : "l"(p));
    return a;
}
__device__ __forceinline__ void ldsm4(uint32_t& r0, uint32_t& r1, uint32_t& r2, uint32_t& r3, uint32_t a) {
    asm volatile("ldmatrix.sync.aligned.m8n8.x4.shared.b16 {%0,%1,%2,%3}, [%4];"
        : "=r"(r0), "=r"(r1), "=r"(r2), "=r"(r3) : "r"(a));
}
__device__ __forceinline__ void ldsm4t(uint32_t& r0, uint32_t& r1, uint32_t& r2, uint32_t& r3, uint32_t a) {
    asm volatile("ldmatrix.sync.aligned.m8n8.x4.trans.shared.b16 {%0,%1,%2,%3}, [%4];"
        : "=r"(r0), "=r"(r1), "=r"(r2), "=r"(r3) : "r"(a));
}
__device__ __forceinline__ void mma16816(float* c,
    uint32_t a0, uint32_t a1, uint32_t a2, uint32_t a3, uint32_t b0, uint32_t b1) {
    asm volatile("mma.sync.aligned.m16n8k16.row.col.f32.bf16.bf16.f32 "
        "{%0,%1,%2,%3}, {%4,%5,%6,%7}, {%8,%9}, {%0,%1,%2,%3};"
        : "+f"(c[0]), "+f"(c[1]), "+f"(c[2]), "+f"(c[3])
        : "r"(a0), "r"(a1), "r"(a2), "r"(a3), "r"(b0), "r"(b1));
}
__device__ __forceinline__ void cpa16(uint32_t s, const void* g) {
    asm volatile("cp.async.cg.shared.global [%0], [%1], 16;" :: "r"(s), "l"(g) : "memory");
}
__device__ __forceinline__ void cpa_commit() {
    asm volatile("cp.async.commit_group;" ::: "memory");
}
template<int N> __device__ __forceinline__ void cpa_wait() {
    asm volatile("cp.async.wait_group %0;" :: "n"(N) : "memory");
}
__device__ __forceinline__ void split2(float a, float b, uint32_t& hi, uint32_t& lo) {
    bf ha = __float2bfloat16(a), hb = __float2bfloat16(b);
    bf la = __float2bfloat16(a - __bfloat162float(ha));
    bf lb = __float2bfloat16(b - __bfloat162float(hb));
    __nv_bfloat162 H, L;
    H.x = ha; H.y = hb; L.x = la; L.y = lb;
    hi = *(uint32_t*)&H; lo = *(uint32_t*)&L;
}
__device__ __forceinline__ void tri_decode(int bidx, int& bi, int& bj) {
    int r = (int)((sqrtf(8.f * bidx + 1.f) - 1.f) * 0.5f);
    while ((r + 1) * (r + 2) / 2 <= bidx) r++;
    while (r * (r + 1) / 2 > bidx) r--;
    bi = r; bj = bidx - r * (r + 1) / 2;
}

// Warp-level split-bf16 GEMM over a K=32 span. NW: n 16-col tiles per warp.
template<int NW, int AS, int BS, int TRANSB>
__device__ __forceinline__ void compute32nw(float (*acc)[4],
    uint32_t Ah, uint32_t Al, uint32_t Bh, uint32_t Bl,
    int ak0, int bk0, int lane, int rowbase, int colbase)
{
    const uint32_t arow = rowbase + (lane & 15);
    #pragma unroll
    for (int ks = 0; ks < 2; ks++) {
        uint32_t ah[4], al[4];
        {
            uint32_t off = (arow * AS + ak0 + ks * 16 + ((lane >> 4) & 1) * 8) * 2;
            ldsm4(ah[0], ah[1], ah[2], ah[3], Ah + off);
            ldsm4(al[0], al[1], al[2], al[3], Al + off);
        }
        uint32_t bh[NW][4], bl[NW][4];
        #pragma unroll
        for (int p = 0; p < NW; p++) {
            if (TRANSB) {
                uint32_t off = ((uint32_t)(bk0 + ks * 16 + (lane & 15)) * BS
                              + colbase + p * 16 + ((lane >> 4) & 1) * 8) * 2;
                ldsm4t(bh[p][0], bh[p][1], bh[p][2], bh[p][3], Bh + off);
                ldsm4t(bl[p][0], bl[p][1], bl[p][2], bl[p][3], Bl + off);
            } else {
                uint32_t off = ((uint32_t)(colbase + p * 16 + (lane & 7) + ((lane >> 4) & 1) * 8) * BS
                              + bk0 + ks * 16 + ((lane >> 3) & 1) * 8) * 2;
                ldsm4(bh[p][0], bh[p][1], bh[p][2], bh[p][3], Bh + off);
                ldsm4(bl[p][0], bl[p][1], bl[p][2], bl[p][3], Bl + off);
            }
        }
        #pragma unroll
        for (int p = 0; p < NW; p++) {
            mma16816(acc[2 * p],     ah[0], ah[1], ah[2], ah[3], bh[p][0], bh[p][1]);
            mma16816(acc[2 * p + 1], ah[0], ah[1], ah[2], ah[3], bh[p][2], bh[p][3]);
        }
        #pragma unroll
        for (int p = 0; p < NW; p++) {
            mma16816(acc[2 * p],     ah[0], ah[1], ah[2], ah[3], bl[p][0], bl[p][1]);
            mma16816(acc[2 * p + 1], ah[0], ah[1], ah[2], ah[3], bl[p][2], bl[p][3]);
        }
        #pragma unroll
        for (int p = 0; p < NW; p++) {
            mma16816(acc[2 * p],     al[0], al[1], al[2], al[3], bh[p][0], bh[p][1]);
            mma16816(acc[2 * p + 1], al[0], al[1], al[2], al[3], bh[p][2], bh[p][3]);
        }
    }
}

// ---------------- prepass: split x and W ----------------
__global__ __launch_bounds__(256) void xsplit_kernel(const float* __restrict__ x) {
    int i = blockIdx.x * 256 + threadIdx.x;
    float4 v = ((const float4*)x)[i];
    uint32_t h0, l0, h1, l1;
    split2(v.x, v.y, h0, l0);
    split2(v.z, v.w, h1, l1);
    ((uint2*)g_xh)[i] = make_uint2(h0, h1);
    ((uint2*)g_xl)[i] = make_uint2(l0, l1);
}
__global__ __launch_bounds__(256) void wsplit_kernel(const float* __restrict__ wq,
    const float* __restrict__ wk, const float* __restrict__ wv) {
    const float* w = blockIdx.y == 0 ? wq : (blockIdx.y == 1 ? wk : wv);
    int i = blockIdx.x * 256 + threadIdx.x;
    float f = w[i];
    bf h = __float2bfloat16(f);
    bf l = __float2bfloat16(f - __bfloat162float(h));
    size_t o = (size_t)blockIdx.y * NE * ND + i;
    g_wh[o] = h; g_wl[o] = l;
}

// ---------------- kernel 1: QKV projection (R8-proven) ----------------
#define QKV_STAGE 27648u
__global__ __launch_bounds__(256) void qkv_mma(
    const float* __restrict__ bq, const float* __restrict__ bk, const float* __restrict__ bv)
{
    extern __shared__ __align__(16) char sm[];
    const uint32_t sb = s2u(sm);
    const int tid = threadIdx.x, lane = tid & 31, wid = tid >> 5;
    const int warpM = wid >> 1, warpN = wid & 1;
    const int m0 = blockIdx.x * 64, mat = blockIdx.y;

    float acc[8][4];
    #pragma unroll
    for (int i = 0; i < 8; i++)
        #pragma unroll
        for (int j = 0; j < 4; j++) acc[i][j] = 0.f;

    auto load_stage = [&](int st, int kb) {
        uint32_t stg = sb + st * QKV_STAGE;
        #pragma unroll
        for (int i = 0; i < 2; i++) {
            int sidx = tid + i * 256;
            int split = sidx >> 8, r = (sidx & 255) >> 2, seg = sidx & 3;
            const bf* src = (split ? g_xl : g_xh) + (size_t)(m0 + r) * NE + kb + seg * 8;
            cpa16(stg + split * 5120 + r * 80 + seg * 16, src);
        }
        #pragma unroll
        for (int i = 0; i < 4; i++) {
            int sidx = tid + i * 256;
            int split = sidx >> 9, r = (sidx & 511) >> 4, seg = sidx & 15;
            const bf* src = (split ? g_wl : g_wh) + ((size_t)mat * NE + kb + r) * ND + seg * 8;
            cpa16(stg + 10240 + split * 8704 + r * 272 + seg * 16, src);
        }
        cpa_commit();
    };

    load_stage(0, 0);
    load_stage(1, 32);
    for (int c = 0; c < 32; c++) {
        if (c >= 31) cpa_wait<0>(); else cpa_wait<1>();
        __syncthreads();
        uint32_t stg = sb + (uint32_t)(c % 3) * QKV_STAGE;
        compute32nw<4, 40, 136, 1>(acc, stg, stg + 5120, stg + 10240, stg + 10240 + 8704,
                                   0, 0, lane, warpM * 16, warpN * 64);
        if (c + 2 < 32) load_stage((c + 2) % 3, (c + 2) * 32);
    }

    const float* bias = mat == 0 ? bq : (mat == 1 ? bk : bv);
    bf* oh = mat == 0 ? g_qh : (mat == 1 ? g_kh : g_vh);
    bf* ol = mat == 0 ? g_ql : (mat == 1 ? g_kl : g_vl);
    const int row = m0 + warpM * 16 + (lane >> 2);
    #pragma unroll
    for (int n = 0; n < 8; n++) {
        int col = warpN * 64 + n * 8 + 2 * (lane & 3);
        float b0 = __ldg(bias + col), b1 = __ldg(bias + col + 1);
        uint32_t H, L;
        split2(acc[n][0] + b0, acc[n][1] + b1, H, L);
        *(uint32_t*)(oh + (size_t)row * ND + col) = H;
        *(uint32_t*)(ol + (size_t)row * ND + col) = L;
        split2(acc[n][2] + b0, acc[n][3] + b1, H, L);
        *(uint32_t*)(oh + (size_t)(row + 8) * ND + col) = H;
        *(uint32_t*)(ol + (size_t)(row + 8) * ND + col) = L;
    }
}

// ---------------- kernel 2: fused scores+softmax+PV tile ----------------
// grid (136, 4, 2), 256 thr. Tile: 64 q-rows x 128 j-tokens. Q/K load + S GEMM
// = scores_mma exact; V load into K's smem slot after S barrier; P stays in
// registers (C->A fragment reuse); partial O + (m,sum) stats to scratch.
// smem: Ah 17408 | Al 17408 | Bh 34816 | Bl 34816 = 104448.
__global__ __launch_bounds__(256) void fused_attn()
{
    extern __shared__ __align__(16) char sm[];
    const uint32_t sb = s2u(sm);
    const int tid = threadIdx.x, lane = tid & 31, wid = tid >> 5;
    const int warpM = wid >> 1, warpN = wid & 1;
    int bi, bj; tri_decode(blockIdx.x, bi, bj);
    const int b = blockIdx.y, z = blockIdx.z;
    const int i0 = bi * 128 + z * 64, j0 = bj * 128;

    float acc[8][4];
    #pragma unroll
    for (int i = 0; i < 8; i++)
        #pragma unroll
        for (int j = 0; j < 4; j++) acc[i][j] = 0.f;

    const size_t qbase = (size_t)(b * NS + i0) * ND;
    const size_t kbase = (size_t)(b * NS + j0) * ND;

    auto load_qk = [&](int kb) {
        #pragma unroll
        for (int i = 0; i < 4; i++) {
            int sidx = tid + i * 256;
            int split = sidx >> 9, r = (sidx & 511) >> 3, seg = sidx & 7;
            const bf* src = (split ? g_ql : g_qh) + qbase + (size_t)r * ND + kb + seg * 8;
            cpa16(sb + split * 17408 + r * 272 + (kb + seg * 8) * 2, src);
        }
        #pragma unroll
        for (int i = 0; i < 8; i++) {
            int sidx = tid + i * 256;
            int split = sidx >> 10, r = (sidx & 1023) >> 3, seg = sidx & 7;
            const bf* src = (split ? g_kl : g_kh) + kbase + (size_t)r * ND + kb + seg * 8;
            cpa16(sb + 34816 + split * 34816 + r * 272 + (kb + seg * 8) * 2, src);
        }
        cpa_commit();
    };
    load_qk(0);
    load_qk(64);
    cpa_wait<1>(); __syncthreads();
    compute32nw<4, 136, 136, 0>(acc, sb, sb + 17408, sb + 34816, sb + 69632,  0,  0, lane, warpM * 16, warpN * 64);
    compute32nw<4, 136, 136, 0>(acc, sb, sb + 17408, sb + 34816, sb + 69632, 32, 32, lane, warpM * 16, warpN * 64);
    cpa_wait<0>(); __syncthreads();
    compute32nw<4, 136, 136, 0>(acc, sb, sb + 17408, sb + 34816, sb + 69632, 64, 64, lane, warpM * 16, warpN * 64);
    compute32nw<4, 136, 136, 0>(acc, sb, sb + 17408, sb + 34816, sb + 69632, 96, 96, lane, warpM * 16, warpN * 64);
    __syncthreads();   // all warps done reading Q and K smem

    // V loads into the (now free) K slot: 128 token rows x 128 d, trans layout
    auto load_v = [&](int kb) {
        #pragma unroll
        for (int i = 0; i < 8; i++) {
            int sidx = tid + i * 256;
            int split = sidx >> 10, r = (sidx & 1023) >> 4, seg = sidx & 15;
            const bf* src = (split ? g_vl : g_vh)
                + (size_t)(b * NS + j0 + kb + r) * ND + seg * 8;
            cpa16(sb + 34816 + split * 34816 + (kb + r) * 272 + seg * 16, src);
        }
        cpa_commit();
    };
    load_v(0);
    load_v(64);

    // scale + causal mask (diag tile only; every row keeps >=1 valid element)
    const float scale = 0.08838834764831845f;
    const int gi0 = i0 + warpM * 16 + (lane >> 2), gi1 = gi0 + 8;
    const bool diag = (bj == bi);
    #pragma unroll
    for (int n = 0; n < 8; n++) {
        int gj = j0 + warpN * 64 + (n >> 1) * 16 + (n & 1) * 8 + 2 * (lane & 3);
        acc[n][0] = (!diag || gj     <= gi0) ? acc[n][0] * scale : -INFINITY;
        acc[n][1] = (!diag || gj + 1 <= gi0) ? acc[n][1] * scale : -INFINITY;
        acc[n][2] = (!diag || gj     <= gi1) ? acc[n][2] * scale : -INFINITY;
        acc[n][3] = (!diag || gj + 1 <= gi1) ? acc[n][3] * scale : -INFINITY;
    }

    // row max: in-warp (4 lanes per row), then across warpN via smem (Q slot dead)
    float m0 = -INFINITY, m1 = -INFINITY;
    #pragma unroll
    for (int n = 0; n < 8; n++) {
        m0 = fmaxf(m0, fmaxf(acc[n][0], acc[n][1]));
        m1 = fmaxf(m1, fmaxf(acc[n][2], acc[n][3]));
    }
    #pragma unroll
    for (int o = 1; o <= 2; o <<= 1) {
        m0 = fmaxf(m0, __shfl_xor_sync(0xffffffffu, m0, o));
        m1 = fmaxf(m1, __shfl_xor_sync(0xffffffffu, m1, o));
    }
    float* st = (float*)sm;                         // [64 rows][2 warpN]
    const int r0 = warpM * 16 + (lane >> 2), r1 = r0 + 8;
    if ((lane & 3) == 0) { st[r0 * 2 + warpN] = m0; st[r1 * 2 + warpN] = m1; }
    __syncthreads();
    m0 = fmaxf(st[r0 * 2], st[r0 * 2 + 1]);
    m1 = fmaxf(st[r1 * 2], st[r1 * 2 + 1]);
    __syncthreads();

    // exp (unnormalized P, <=1) + row sum
    float s0 = 0.f, s1 = 0.f;
    #pragma unroll
    for (int n = 0; n < 8; n++) {
        acc[n][0] = __expf(acc[n][0] - m0); s0 += acc[n][0];
        acc[n][1] = __expf(acc[n][1] - m0); s0 += acc[n][1];
        acc[n][2] = __expf(acc[n][2] - m1); s1 += acc[n][2];
        acc[n][3] = __expf(acc[n][3] - m1); s1 += acc[n][3];
    }
    #pragma unroll
    for (int o = 1; o <= 2; o <<= 1) {
        s0 += __shfl_xor_sync(0xffffffffu, s0, o);
        s1 += __shfl_xor_sync(0xffffffffu, s1, o);
    }
    if ((lane & 3) == 0) { st[r0 * 2 + warpN] = s0; st[r1 * 2 + warpN] = s1; }
    __syncthreads();
    s0 = st[r0 * 2] + st[r0 * 2 + 1];
    s1 = st[r1 * 2] + st[r1 * 2 + 1];
    if (warpN == 0 && (lane & 3) == 0) {
        g_stat[((size_t)b * NS + gi0) * 16 + bj] = make_float2(m0, s0);
        g_stat[((size_t)b * NS + gi1) * 16 + bj] = make_float2(m1, s1);
    }

    // C-fragment -> A-fragment repack: chunk c covers warp k-cols [16c,16c+16)
    uint32_t ph[4][4], pl[4][4];
    #pragma unroll
    for (int c = 0; c < 4; c++) {
        split2(acc[2 * c][0],     acc[2 * c][1],     ph[c][0], pl[c][0]);  // a0
        split2(acc[2 * c][2],     acc[2 * c][3],     ph[c][1], pl[c][1]);  // a1
        split2(acc[2 * c + 1][0], acc[2 * c + 1][1], ph[c][2], pl[c][2]);  // a2
        split2(acc[2 * c + 1][2], acc[2 * c + 1][3], ph[c][3], pl[c][3]);  // a3
    }

    float ao[16][4];
    #pragma unroll
    for (int n = 0; n < 16; n++)
        #pragma unroll
        for (int v = 0; v < 4; v++) ao[n][v] = 0.f;

    cpa_wait<0>(); __syncthreads();   // V resident

    // PV: A = P fragments (regs), B = V [token][d] trans. Partial-k (warp's 64).
    const uint32_t Vh = sb + 34816, Vl = sb + 69632;
    #pragma unroll
    for (int c = 0; c < 4; c++) {
        const int bk = warpN * 64 + c * 16;
        #pragma unroll
        for (int p = 0; p < 8; p++) {
            uint32_t off = ((uint32_t)(bk + (lane & 15)) * 136
                          + p * 16 + ((lane >> 4) & 1) * 8) * 2;
            uint32_t h0, h1, h2, h3, l0, l1, l2, l3;
            ldsm4t(h0, h1, h2, h3, Vh + off);
            ldsm4t(l0, l1, l2, l3, Vl + off);
            mma16816(ao[2 * p],     ph[c][0], ph[c][1], ph[c][2], ph[c][3], h0, h1);
            mma16816(ao[2 * p + 1], ph[c][0], ph[c][1], ph[c][2], ph[c][3], h2, h3);
            mma16816(ao[2 * p],     ph[c][0], ph[c][1], ph[c][2], ph[c][3], l0, l1);
            mma16816(ao[2 * p + 1], ph[c][0], ph[c][1], ph[c][2], ph[c][3], l2, l3);
            mma16816(ao[2 * p],     pl[c][0], pl[c][1], pl[c][2], pl[c][3], h0, h1);
            mma16816(ao[2 * p + 1], pl[c][0], pl[c][1], pl[c][2], pl[c][3], h2, h3);
        }
    }

    // reduce the two warpN k-halves via smem (Q slot), then store partial O
    float* red = (float*)sm;          // 4 warpM x 16 rows x 128 d = 32 KB
    __syncthreads();
    if (warpN == 1) {
        #pragma unroll
        for (int n = 0; n < 16; n++) {
            int d = (n >> 1) * 16 + (n & 1) * 8 + 2 * (lane & 3);
            *(float2*)&red[(warpM * 16 + (lane >> 2)) * 128 + d]     = make_float2(ao[n][0], ao[n][1]);
            *(float2*)&red[(warpM * 16 + (lane >> 2) + 8) * 128 + d] = make_float2(ao[n][2], ao[n][3]);
        }
    }
    __syncthreads();
    if (warpN == 0) {
        float* po = g_po + (((size_t)b * 16 + bi) * 16 + bj) * 16384
                  + (size_t)(z * 64 + warpM * 16) * 128;
        #pragma unroll
        for (int n = 0; n < 16; n++) {
            int d = (n >> 1) * 16 + (n & 1) * 8 + 2 * (lane & 3);
            int rr = lane >> 2;
            float2 q0 = *(float2*)&red[(warpM * 16 + rr) * 128 + d];
            float2 q1 = *(float2*)&red[(warpM * 16 + rr + 8) * 128 + d];
            *(float2*)&po[rr * 128 + d]       = make_float2(ao[n][0] + q0.x, ao[n][1] + q0.y);
            *(float2*)&po[(rr + 8) * 128 + d] = make_float2(ao[n][2] + q1.x, ao[n][3] + q1.y);
        }
    }
}

// ---------------- kernel 3: combine partial O tiles ----------------
__global__ __launch_bounds__(128) void combine_kernel(float* __restrict__ out)
{
    const int rowid = blockIdx.x;
    const int b = rowid >> 11, i = rowid & 2047;
    const int bi = i >> 7, nt = bi + 1;
    const int d = threadIdx.x;
    const float2* st = g_stat + ((size_t)b * NS + i) * 16;

    float m = -INFINITY;
    for (int t = 0; t < nt; t++) m = fmaxf(m, st[t].x);
    float den = 0.f;
    for (int t = 0; t < nt; t++) den += st[t].y * __expf(st[t].x - m);

    const float* pob = g_po + ((size_t)b * 16 + bi) * 16 * 16384 + (size_t)(i & 127) * 128 + d;
    float o = 0.f;
    for (int t = 0; t < nt; t++)
        o += __expf(st[t].x - m) * pob[(size_t)t * 16384];
    out[(size_t)rowid * ND + d] = o / den;
}

// ---------------- launch ----------------
extern "C" void kernel_launch(void* const* d_in, const int* in_sizes, int n_in,
                              void* d_out, int out_size) {
    const float* x  = (const float*)d_in[0];
    const float* wq = (const float*)d_in[1];
    const float* bq = (const float*)d_in[2];
    const float* wk = (const float*)d_in[3];
    const float* bk = (const float*)d_in[4];
    const float* wv = (const float*)d_in[5];
    const float* bv = (const float*)d_in[6];
    float* out = (float*)d_out;

    static int inited = 0;
    if (!inited) {
        cudaFuncSetAttribute(qkv_mma,    cudaFuncAttributeMaxDynamicSharedMemorySize, 3 * QKV_STAGE);
        cudaFuncSetAttribute(fused_attn, cudaFuncAttributeMaxDynamicSharedMemorySize, 104448);
        inited = 1;
    }

    xsplit_kernel<<<NTOK * NE / 1024, 256>>>(x);
    wsplit_kernel<<<dim3(NE * ND / 256, 3), 256>>>(wq, wk, wv);
    qkv_mma<<<dim3(128, 3), 256, 3 * QKV_STAGE>>>(bq, bk, bv);
    fused_attn<<<dim3(136, NB, 2), 256, 104448>>>();
    combine_kernel<<<NTOK, 128>>>(out);
}